// round 2
// baseline (speedup 1.0000x reference)
#include <cuda_runtime.h>

#define NUM_SEG 100000
#define DIM 32

// Scratch: per-segment counts (allocation-free rule => __device__ global)
__device__ float g_counts[NUM_SEG];

// Zero the output sums and the counts. out has NUM_SEG*DIM floats.
__global__ void zero_kernel(float* __restrict__ out, int total) {
    int i = blockIdx.x * blockDim.x + threadIdx.x;
    if (i < total) out[i] = 0.0f;
    if (i < NUM_SEG) g_counts[i] = 0.0f;
}

// One thread per float4 chunk of a row: 8 threads per row of 32 floats.
// Perfectly coalesced loads (warp reads 512 contiguous bytes), and one
// 16-byte vector RED per thread -> 4x fewer L2 atomic ops than scalar.
__global__ void scatter_kernel(const float4* __restrict__ x4,
                               const int* __restrict__ index,
                               float* __restrict__ out,
                               long long nchunks) {
    long long gid = (long long)blockIdx.x * blockDim.x + threadIdx.x;
    if (gid >= nchunks) return;

    int row = (int)(gid >> 3);
    int q   = (int)(gid & 7);

    int seg = index[row];
    if ((unsigned)seg >= NUM_SEG) return;  // safety: wrong dtype -> wrong answer, not crash

    float4 v = x4[gid];

    float* addr = out + (long long)seg * DIM + q * 4;
    asm volatile("red.global.add.v4.f32 [%0], {%1, %2, %3, %4};"
                 :: "l"(addr), "f"(v.x), "f"(v.y), "f"(v.z), "f"(v.w)
                 : "memory");

    if (q == 0) {
        atomicAdd(&g_counts[seg], 1.0f);
    }
}

// out[i] = sum[i] / max(count[i/32], 1)
__global__ void divide_kernel(float* __restrict__ out, int total) {
    int i = blockIdx.x * blockDim.x + threadIdx.x;
    if (i < total) {
        float c = g_counts[i >> 5];  // DIM == 32
        out[i] = out[i] / fmaxf(c, 1.0f);
    }
}

extern "C" void kernel_launch(void* const* d_in, const int* in_sizes, int n_in,
                              void* d_out, int out_size) {
    const float4* x4 = (const float4*)d_in[0];
    const int* index = (const int*)d_in[1];
    float* out = (float*)d_out;

    int nrows = in_sizes[1];                   // 4,000,000
    long long nchunks = (long long)nrows * 8;  // 8 float4 per row (DIM=32)
    int total = out_size;                      // NUM_SEG * DIM

    const int TPB = 256;

    int zb = (total + TPB - 1) / TPB;
    zero_kernel<<<zb, TPB>>>(out, total);

    int sb = (int)((nchunks + TPB - 1) / TPB);
    scatter_kernel<<<sb, TPB>>>(x4, index, out, nchunks);

    int db = (total + TPB - 1) / TPB;
    divide_kernel<<<db, TPB>>>(out, total);
}

// round 3
// speedup vs baseline: 1.1128x; 1.1128x over previous
#include <cuda_runtime.h>
#include <cstdint>

#define NUM_SEG 100000
#define DIM 32
#define TPB 256
#define ROWS_PER_BLK 256
#define CHUNKS_PER_BLK (ROWS_PER_BLK * 8)   // float4 chunks (32 floats = 8 chunks/row)

// Scratch: per-segment counts (allocation-free rule => __device__ global)
__device__ float g_counts[NUM_SEG];

__device__ __forceinline__ uint32_t smem_u32(const void* p) {
    uint32_t a;
    asm("{ .reg .u64 t; cvta.to.shared.u64 t, %1; cvt.u32.u64 %0, t; }" : "=r"(a) : "l"(p));
    return a;
}

// Stage 256 contiguous rows (32 KB) in smem via coalesced float4 loads, then
// each thread issues ONE cp.reduce.async.bulk (128 B f32-add) for its row.
// This moves the reduction off the SM LSU (which prices REDG per-lane) onto
// the TMA/L2 path.
__global__ void __launch_bounds__(TPB) scatter_kernel(
    const float4* __restrict__ x4,
    const int* __restrict__ index,
    float* __restrict__ out,
    int nrows)
{
    __shared__ float4 tile[CHUNKS_PER_BLK];   // 32 KB

    int t = threadIdx.x;
    long long base_chunk = (long long)blockIdx.x * CHUNKS_PER_BLK;
    long long nchunks = (long long)nrows * 8;

    #pragma unroll
    for (int k = 0; k < 8; k++) {
        long long c = base_chunk + t + k * TPB;
        if (c < nchunks) tile[t + k * TPB] = x4[c];
    }
    __syncthreads();
    // Order generic-proxy smem writes before async-proxy (TMA) reads.
    asm volatile("fence.proxy.async.shared::cta;" ::: "memory");

    int row = blockIdx.x * ROWS_PER_BLK + t;
    if (row < nrows) {
        int seg = index[row];
        if ((unsigned)seg < NUM_SEG) {
            uint32_t saddr = smem_u32(&tile[t * 8]);
            float* gdst = out + (long long)seg * DIM;
            asm volatile(
                "cp.reduce.async.bulk.global.shared::cta.bulk_group.add.f32 [%0], [%1], %2;"
                :: "l"(gdst), "r"(saddr), "r"(DIM * 4) : "memory");
            atomicAdd(&g_counts[seg], 1.0f);
        }
    }
    // Drain bulk ops before CTA exit (smem is read asynchronously).
    asm volatile("cp.async.bulk.commit_group;" ::: "memory");
    asm volatile("cp.async.bulk.wait_group 0;" ::: "memory");
}

// out[i] = sum[i] / max(count[i/32], 1)
__global__ void divide_kernel(float* __restrict__ out, int total) {
    int i = blockIdx.x * blockDim.x + threadIdx.x;
    if (i < total) {
        float c = g_counts[i >> 5];  // DIM == 32
        out[i] = out[i] / fmaxf(c, 1.0f);
    }
}

extern "C" void kernel_launch(void* const* d_in, const int* in_sizes, int n_in,
                              void* d_out, int out_size) {
    const float4* x4 = (const float4*)d_in[0];
    const int* index = (const int*)d_in[1];
    float* out = (float*)d_out;

    int nrows = in_sizes[1];   // 4,000,000
    int total = out_size;      // NUM_SEG * DIM

    // Zero sums + counts via memset nodes (cheaper than a kernel).
    void* counts_ptr = nullptr;
    cudaGetSymbolAddress(&counts_ptr, g_counts);
    cudaMemsetAsync(out, 0, (size_t)total * sizeof(float), 0);
    cudaMemsetAsync(counts_ptr, 0, (size_t)NUM_SEG * sizeof(float), 0);

    int sb = (nrows + ROWS_PER_BLK - 1) / ROWS_PER_BLK;
    scatter_kernel<<<sb, TPB>>>(x4, index, out, nrows);

    int db = (total + TPB - 1) / TPB;
    divide_kernel<<<db, TPB>>>(out, total);
}

// round 4
// speedup vs baseline: 1.1765x; 1.0573x over previous
#include <cuda_runtime.h>
#include <cstdint>

#define NUM_SEG 100000
#define DIM 32
#define TPB 256
#define ROWS_PER_BLK 256
#define CHUNKS_PER_BLK (ROWS_PER_BLK * 8)   // float4 chunks (32 floats = 8/row)

// Scratch: per-segment counts (allocation-free rule => __device__ global)
__device__ float g_counts[NUM_SEG];

__device__ __forceinline__ uint32_t smem_u32(const void* p) {
    uint32_t a;
    asm("{ .reg .u64 t; cvta.to.shared.u64 t, %1; cvt.u32.u64 %0, t; }" : "=r"(a) : "l"(p));
    return a;
}

// Hybrid scatter: blocks [0, tma_blocks) push sums through the TMA engine
// (cp.reduce.async.bulk), the rest through the LSU (red.global.v4). The two
// engines run concurrently, each on its own slice of rows, so neither is the
// chip-wide bottleneck; target is the DRAM read floor.
__global__ void __launch_bounds__(TPB) scatter_kernel(
    const float4* __restrict__ x4,
    const int* __restrict__ index,
    float* __restrict__ out,
    int nrows, int tma_blocks)
{
    __shared__ float4 tile[CHUNKS_PER_BLK];   // 32 KB (TMA path only)
    __shared__ int segs[ROWS_PER_BLK];        // (RED path only)

    int t = threadIdx.x;
    long long base_chunk = (long long)blockIdx.x * CHUNKS_PER_BLK;
    long long nchunks = (long long)nrows * 8;
    int row0 = blockIdx.x * ROWS_PER_BLK;

    if (blockIdx.x < tma_blocks) {
        // ---- TMA bulk-reduce path ----
        #pragma unroll
        for (int k = 0; k < 8; k++) {
            long long c = base_chunk + t + k * TPB;
            if (c < nchunks) tile[t + k * TPB] = x4[c];
        }
        __syncthreads();
        asm volatile("fence.proxy.async.shared::cta;" ::: "memory");

        int row = row0 + t;
        if (row < nrows) {
            int seg = index[row];
            if ((unsigned)seg < NUM_SEG) {
                uint32_t saddr = smem_u32(&tile[t * 8]);
                float* gdst = out + (long long)seg * DIM;
                asm volatile(
                    "cp.reduce.async.bulk.global.shared::cta.bulk_group.add.f32 [%0], [%1], %2;"
                    :: "l"(gdst), "r"(saddr), "r"(DIM * 4) : "memory");
                atomicAdd(&g_counts[seg], 1.0f);
            }
        }
        asm volatile("cp.async.bulk.commit_group;" ::: "memory");
        asm volatile("cp.async.bulk.wait_group 0;" ::: "memory");
    } else {
        // ---- LSU red.global path ----
        int row = row0 + t;
        int myseg = -1;
        if (row < nrows) {
            myseg = index[row];
            if ((unsigned)myseg >= NUM_SEG) myseg = -1;
        }
        segs[t] = myseg;
        __syncthreads();

        #pragma unroll
        for (int k = 0; k < 8; k++) {
            long long c = base_chunk + t + k * TPB;
            if (c < nchunks) {
                int local = t + k * TPB;
                int seg = segs[local >> 3];
                if (seg >= 0) {
                    float4 v = x4[c];
                    float* addr = out + (long long)seg * DIM + (local & 7) * 4;
                    asm volatile("red.global.add.v4.f32 [%0], {%1, %2, %3, %4};"
                                 :: "l"(addr), "f"(v.x), "f"(v.y), "f"(v.z), "f"(v.w)
                                 : "memory");
                }
            }
        }
        if (myseg >= 0) atomicAdd(&g_counts[myseg], 1.0f);
    }
}

// Vectorized divide: one thread per float4; reciprocal once per thread.
__global__ void divide_kernel(float4* __restrict__ out4, int total4) {
    int i = blockIdx.x * blockDim.x + threadIdx.x;
    if (i < total4) {
        float c = g_counts[i >> 3];          // 8 float4 per row of 32
        float r = __frcp_rn(fmaxf(c, 1.0f));
        float4 v = out4[i];
        v.x *= r; v.y *= r; v.z *= r; v.w *= r;
        out4[i] = v;
    }
}

extern "C" void kernel_launch(void* const* d_in, const int* in_sizes, int n_in,
                              void* d_out, int out_size) {
    const float4* x4 = (const float4*)d_in[0];
    const int* index = (const int*)d_in[1];
    float* out = (float*)d_out;

    int nrows = in_sizes[1];   // 4,000,000
    int total = out_size;      // NUM_SEG * DIM

    void* counts_ptr = nullptr;
    cudaGetSymbolAddress(&counts_ptr, g_counts);
    cudaMemsetAsync(out, 0, (size_t)total * sizeof(float), 0);
    cudaMemsetAsync(counts_ptr, 0, (size_t)NUM_SEG * sizeof(float), 0);

    int sb = (nrows + ROWS_PER_BLK - 1) / ROWS_PER_BLK;
    int tma_blocks = (int)((long long)sb * 17 / 32);   // ~53% via TMA engine
    scatter_kernel<<<sb, TPB>>>(x4, index, out, nrows, tma_blocks);

    int total4 = total / 4;
    int db = (total4 + TPB - 1) / TPB;
    divide_kernel<<<db, TPB>>>((float4*)out, total4);
}